// round 6
// baseline (speedup 1.0000x reference)
#include <cuda_runtime.h>
#include <math.h>

#define ND 64
#define ND2 128
#define NHW 4096
#define NBT 64
#define NTT 16
#define NBB 4
#define NTOT (NBT*ND*NHW)
#define PADW 66
#define PLANEP (PADW*PADW)
#define RP 66

typedef unsigned long long u64;

__device__ float g_pad[(size_t)NBT*ND2*PLANEP];   // zero-init: borders stay 0 forever
__device__ float g_a[NTOT], g_b[NTOT], g_c[NTOT], g_d[NTOT];
__device__ float g_w[128*128*9];                  // conv weights transposed [ic*9+tap][oc]
__device__ float g_twr[4096], g_twi[4096];        // DFT twiddle table F[u][w], symmetric

// ---- f32x2 helpers ----
__device__ __forceinline__ u64 pk(float lo, float hi) {
    u64 r; asm("mov.b64 %0, {%1,%2};" : "=l"(r) : "f"(lo), "f"(hi)); return r;
}
__device__ __forceinline__ u64 bc(float v) { return pk(v, v); }
__device__ __forceinline__ void fma2(u64& d, u64 a, u64 b) {
    asm("fma.rn.f32x2 %0, %1, %2, %0;" : "+l"(d) : "l"(a), "l"(b));
}
__device__ __forceinline__ float2 up(u64 v) {
    float2 f; asm("mov.b64 {%0,%1}, %2;" : "=f"(f.x), "=f"(f.y) : "l"(v)); return f;
}
__device__ __forceinline__ u64 lds2(const float* p) { return *(const u64*)p; }
__device__ __forceinline__ u64 ldg2(const float* p) { return *(const u64*)p; }

// ---------- init: conv weight transpose + twiddle table ----------
__global__ void k_init(const float* __restrict__ cw) {
    int i = blockIdx.x*blockDim.x + threadIdx.x;
    if (i < 4096) {
        const float W64 = 6.28318530717958647692f/64.f;
        int u = i>>6, w = i&63, t = (u*w)&63;
        float sv, cv; sincosf(-W64*(float)t, &sv, &cv);
        g_twr[i] = cv; g_twi[i] = sv;
    }
    if (i < 128*128*9) {
        int oc = i / 1152, rem = i - oc*1152;
        g_w[rem*128 + oc] = cw[i];
    }
}

// ---------- complex LayerNorm over 128-ch [re|im] ----------
template<int MODE>
__global__ void k_ln(const float* __restrict__ xr, const float* __restrict__ xi,
                     const float* __restrict__ gam, const float* __restrict__ bet) {
    __shared__ float s[128][64];
    __shared__ float ps[4][64], pq[4][64], mb[64], rb[64];
    int h = blockIdx.x, n = blockIdx.y;
    int tx = threadIdx.x, ty = threadIdx.y;
    int base = n*(ND*NHW) + h*64 + tx;
    float sum = 0.f, sq = 0.f;
    for (int j = 0; j < 32; j++) {
        int c = ty*32 + j; float v;
        if (MODE == 0) v = (c < 64) ? xr[base + c*NHW] : xi[base + (c-64)*NHW];
        else           v = (c < 64) ? g_a[base + c*NHW] : g_b[base + (c-64)*NHW];
        s[c][tx] = v; sum += v; sq += v*v;
    }
    ps[ty][tx] = sum; pq[ty][tx] = sq;
    __syncthreads();
    if (ty == 0) {
        float S = ps[0][tx]+ps[1][tx]+ps[2][tx]+ps[3][tx];
        float Q = pq[0][tx]+pq[1][tx]+pq[2][tx]+pq[3][tx];
        float m = S*(1.f/128.f);
        mb[tx] = m; rb[tx] = rsqrtf(Q*(1.f/128.f) - m*m + 1e-5f);
    }
    __syncthreads();
    float m = mb[tx], r = rb[tx];
    for (int j = 0; j < 32; j++) {
        int c = ty*32 + j;
        float y = (s[c][tx] - m)*r*gam[c] + bet[c];
        if (MODE == 0) g_pad[((size_t)(n*ND2 + c))*PLANEP + (h+1)*PADW + tx+1] = y;
        else { if (c < 64) g_c[base + c*NHW] = y; else g_d[base + (c-64)*NHW] = y; }
    }
}

// ---------- direct 3x3 conv 128->128, f32x2, ic chunked by 8, 3 CTAs/SM ----------
#define CONV_SM ((3*8*66 + 8*9*128)*4)
__global__ __launch_bounds__(256, 3) void k_conv(const float* __restrict__ cb) {
    extern __shared__ float sm[];
    float* sin_ = sm;              // [3][8][66]  (per ic chunk)
    float* sw   = sm + 3*8*66;     // [8*9][128]  (row = icl*9+tap, col = oc)
    int h = blockIdx.x, n = blockIdx.y, tid = threadIdx.x;
    const float* src = g_pad + (size_t)n*ND2*PLANEP;
    int wg = tid & 15, og = tid >> 4, w0 = wg*4;
    u64 accp[4][4];
    #pragma unroll
    for (int a = 0; a < 4; a++)
        for (int b2 = 0; b2 < 4; b2++) accp[a][b2] = 0ull;
    for (int icc = 0; icc < 16; icc++) {
        __syncthreads();
        for (int l = tid; l < 3*8*66; l += 256) {
            int r = l/(8*66), rem = l - r*(8*66);
            int icl = rem/66, c = rem - icl*66;
            sin_[l] = src[(size_t)(icc*8+icl)*PLANEP + (h + r)*PADW + c];
        }
        for (int l = tid; l < 8*9*128; l += 256)
            sw[l] = g_w[icc*8*9*128 + l];
        __syncthreads();
        #pragma unroll 1
        for (int icl = 0; icl < 8; icl++) {
            float inv[3][6];
            #pragma unroll
            for (int r = 0; r < 3; r++) {
                float2 t0 = *(const float2*)&sin_[(r*8+icl)*66 + w0];
                float2 t1 = *(const float2*)&sin_[(r*8+icl)*66 + w0 + 2];
                float2 t2 = *(const float2*)&sin_[(r*8+icl)*66 + w0 + 4];
                inv[r][0]=t0.x; inv[r][1]=t0.y; inv[r][2]=t1.x;
                inv[r][3]=t1.y; inv[r][4]=t2.x; inv[r][5]=t2.y;
            }
            #pragma unroll
            for (int ky = 0; ky < 3; ky++)
                for (int kx = 0; kx < 3; kx++) {
                    int tap = ky*3 + kx;
                    u64 b0 = bc(inv[ky][kx]),   b1 = bc(inv[ky][kx+1]);
                    u64 b2 = bc(inv[ky][kx+2]), b3 = bc(inv[ky][kx+3]);
                    const u64* wp = (const u64*)&sw[(icl*9+tap)*128 + og*8];
                    #pragma unroll
                    for (int op = 0; op < 4; op++) {
                        u64 wv = wp[op];
                        fma2(accp[op][0], wv, b0);
                        fma2(accp[op][1], wv, b1);
                        fma2(accp[op][2], wv, b2);
                        fma2(accp[op][3], wv, b3);
                    }
                }
        }
    }
    int ob = n*(ND*NHW) + h*64 + w0;
    #pragma unroll
    for (int op = 0; op < 4; op++) {
        int oc0 = og*8 + 2*op;
        float bia0 = cb[oc0], bia1 = cb[oc0+1];
        #pragma unroll
        for (int xw = 0; xw < 4; xw++) {
            float2 v = up(accp[op][xw]);
            float v0 = v.x + bia0, v1 = v.y + bia1;
            if (oc0 < 64) { g_a[ob + oc0*NHW + xw] = v0; g_a[ob + (oc0+1)*NHW + xw] = v1; }
            else { g_b[ob + (oc0-64)*NHW + xw] = v0; g_b[ob + (oc0-63)*NHW + xw] = v1; }
        }
    }
}

// ---------- spectral IFFT2(FFT2(x)*W), twiddles from global, 3 CTAs/SM ----------
#define FFT_SM (4*64*RP*4)
__global__ __launch_bounds__(256, 3) void k_fft(const float* __restrict__ swr,
                                                const float* __restrict__ swi,
                                                const float* __restrict__ xin_r,
                                                const float* __restrict__ xin_i,
                                                const float* __restrict__ gate) {
    extern __shared__ float sm[];
    float *ar = sm, *ai = ar+64*RP, *br = ai+64*RP, *bi = br+64*RP;
    int d = blockIdx.x, n = blockIdx.y, tid = threadIdx.x;
    const float* pr0 = g_pad + ((size_t)(n*ND2 + d))*PLANEP;
    const float* pi0 = g_pad + ((size_t)(n*ND2 + 64 + d))*PLANEP;
    for (int l = tid; l < 4096; l += 256) {
        int hh = l>>6, ww = l&63;
        ar[hh*RP+ww] = pr0[(hh+1)*PADW + ww+1];
        ai[hh*RP+ww] = pi0[(hh+1)*PADW + ww+1];
    }
    __syncthreads();
    int r0 = (tid>>4)*4, c0 = (tid&15)*4;
    { // pass1: b[h][v] = sum_w a[h][w] F[v][w]
        u64 pr_[4][2] = {}, pi_[4][2] = {};
        for (int w = 0; w < 64; w++) {
            u64 g0 = ldg2(&g_twr[w*64+c0]), g1 = ldg2(&g_twr[w*64+c0+2]);
            u64 q0 = ldg2(&g_twi[w*64+c0]), q1 = ldg2(&g_twi[w*64+c0+2]);
            #pragma unroll
            for (int i = 0; i < 4; i++) {
                float xr1 = ar[(r0+i)*RP+w], xi1 = ai[(r0+i)*RP+w];
                u64 bxr = bc(xr1), bxi = bc(xi1), bnxi = bc(-xi1);
                fma2(pr_[i][0], bxr, g0); fma2(pr_[i][0], bnxi, q0);
                fma2(pr_[i][1], bxr, g1); fma2(pr_[i][1], bnxi, q1);
                fma2(pi_[i][0], bxr, q0); fma2(pi_[i][0], bxi, g0);
                fma2(pi_[i][1], bxr, q1); fma2(pi_[i][1], bxi, g1);
            }
        }
        #pragma unroll
        for (int i = 0; i < 4; i++) {
            *(float2*)&br[(r0+i)*RP+c0]   = up(pr_[i][0]);
            *(float2*)&br[(r0+i)*RP+c0+2] = up(pr_[i][1]);
            *(float2*)&bi[(r0+i)*RP+c0]   = up(pi_[i][0]);
            *(float2*)&bi[(r0+i)*RP+c0+2] = up(pi_[i][1]);
        }
    }
    __syncthreads();
    { // pass2: a[u][v] = sum_h F[u][h] b[h][v]
        u64 pr_[4][2] = {}, pi_[4][2] = {};
        for (int hs = 0; hs < 64; hs++) {
            u64 x0 = lds2(&br[hs*RP+c0]), x1 = lds2(&br[hs*RP+c0+2]);
            u64 y0 = lds2(&bi[hs*RP+c0]), y1 = lds2(&bi[hs*RP+c0+2]);
            float2 ga = *(const float2*)&g_twr[hs*64+r0], gb2 = *(const float2*)&g_twr[hs*64+r0+2];
            float2 qa = *(const float2*)&g_twi[hs*64+r0], qb = *(const float2*)&g_twi[hs*64+r0+2];
            float grs[4] = {ga.x, ga.y, gb2.x, gb2.y};
            float gis[4] = {qa.x, qa.y, qb.x, qb.y};
            #pragma unroll
            for (int i = 0; i < 4; i++) {
                u64 bgr = bc(grs[i]), bgi = bc(gis[i]), bngi = bc(-gis[i]);
                fma2(pr_[i][0], bgr, x0); fma2(pr_[i][0], bngi, y0);
                fma2(pr_[i][1], bgr, x1); fma2(pr_[i][1], bngi, y1);
                fma2(pi_[i][0], bgr, y0); fma2(pi_[i][0], bgi, x0);
                fma2(pi_[i][1], bgr, y1); fma2(pi_[i][1], bgi, x1);
            }
        }
        __syncthreads();
        #pragma unroll
        for (int i = 0; i < 4; i++) {
            *(float2*)&ar[(r0+i)*RP+c0]   = up(pr_[i][0]);
            *(float2*)&ar[(r0+i)*RP+c0+2] = up(pr_[i][1]);
            *(float2*)&ai[(r0+i)*RP+c0]   = up(pi_[i][0]);
            *(float2*)&ai[(r0+i)*RP+c0+2] = up(pi_[i][1]);
        }
    }
    __syncthreads();
    { // pointwise * spec_w[d]
        const float* wr2 = swr + d*NHW; const float* wi2 = swi + d*NHW;
        for (int l = tid; l < 4096; l += 256) {
            int u = l>>6, v = l&63;
            float zr = ar[u*RP+v], zi = ai[u*RP+v];
            float wr_ = wr2[l], wi_ = wi2[l];
            ar[u*RP+v] = zr*wr_ - zi*wi_;
            ai[u*RP+v] = zr*wi_ + zi*wr_;
        }
    }
    __syncthreads();
    { // pass3: b[h][v] = sum_u conj(F)[h][u] a[u][v]
        u64 pr_[4][2] = {}, pi_[4][2] = {};
        for (int us = 0; us < 64; us++) {
            u64 x0 = lds2(&ar[us*RP+c0]), x1 = lds2(&ar[us*RP+c0+2]);
            u64 y0 = lds2(&ai[us*RP+c0]), y1 = lds2(&ai[us*RP+c0+2]);
            float2 ga = *(const float2*)&g_twr[us*64+r0], gb2 = *(const float2*)&g_twr[us*64+r0+2];
            float2 qa = *(const float2*)&g_twi[us*64+r0], qb = *(const float2*)&g_twi[us*64+r0+2];
            float grs[4] = {ga.x, ga.y, gb2.x, gb2.y};
            float gis[4] = {qa.x, qa.y, qb.x, qb.y};
            #pragma unroll
            for (int i = 0; i < 4; i++) {
                u64 bgr = bc(grs[i]), bgi = bc(gis[i]), bngi = bc(-gis[i]);
                fma2(pr_[i][0], bgr, x0); fma2(pr_[i][0], bgi, y0);
                fma2(pr_[i][1], bgr, x1); fma2(pr_[i][1], bgi, y1);
                fma2(pi_[i][0], bgr, y0); fma2(pi_[i][0], bngi, x0);
                fma2(pi_[i][1], bgr, y1); fma2(pi_[i][1], bngi, x1);
            }
        }
        #pragma unroll
        for (int i = 0; i < 4; i++) {
            *(float2*)&br[(r0+i)*RP+c0]   = up(pr_[i][0]);
            *(float2*)&br[(r0+i)*RP+c0+2] = up(pr_[i][1]);
            *(float2*)&bi[(r0+i)*RP+c0]   = up(pi_[i][0]);
            *(float2*)&bi[(r0+i)*RP+c0+2] = up(pi_[i][1]);
        }
    }
    __syncthreads();
    { // pass4 + fused combine: x1 = g*cliff + (1-g)*spec + x_in -> g_a/g_b
        u64 pr_[4][2] = {}, pi_[4][2] = {};
        for (int vs = 0; vs < 64; vs++) {
            u64 g0 = ldg2(&g_twr[vs*64+c0]), g1 = ldg2(&g_twr[vs*64+c0+2]);
            u64 q0 = ldg2(&g_twi[vs*64+c0]), q1 = ldg2(&g_twi[vs*64+c0+2]);
            #pragma unroll
            for (int i = 0; i < 4; i++) {
                float xr1 = br[(r0+i)*RP+vs], xi1 = bi[(r0+i)*RP+vs];
                u64 bxr = bc(xr1), bxi = bc(xi1), bnxr = bc(-xr1);
                fma2(pr_[i][0], bxr, g0); fma2(pr_[i][0], bxi, q0);
                fma2(pr_[i][1], bxr, g1); fma2(pr_[i][1], bxi, q1);
                fma2(pi_[i][0], bxi, g0); fma2(pi_[i][0], bnxr, q0);
                fma2(pi_[i][1], bxi, g1); fma2(pi_[i][1], bnxr, q1);
            }
        }
        const float sc = 1.f/4096.f;
        float g = gate[0], omg = 1.f - g;
        int base = n*ND*NHW + d*NHW;
        #pragma unroll
        for (int i = 0; i < 4; i++)
            for (int jp = 0; jp < 2; jp++) {
                int idx = base + (r0+i)*64 + c0 + 2*jp;
                float2 sr = up(pr_[i][jp]);
                float2 si = up(pi_[i][jp]);
                float2 clr = *(const float2*)&g_a[idx];
                float2 cli = *(const float2*)&g_b[idx];
                float2 inr = *(const float2*)&xin_r[idx];
                float2 ini = *(const float2*)&xin_i[idx];
                float2 orr, oii;
                orr.x = g*clr.x + omg*sr.x*sc + inr.x;
                orr.y = g*clr.y + omg*sr.y*sc + inr.y;
                oii.x = g*cli.x + omg*si.x*sc + ini.x;
                oii.y = g*cli.y + omg*si.y*sc + ini.y;
                *(float2*)&g_a[idx] = orr;
                *(float2*)&g_b[idx] = oii;
            }
    }
}

// ---------- complex encode GEMM (in place g_c/g_d) ----------
#define GE_SM (4*64*RP*4)
__global__ __launch_bounds__(256, 3) void k_enc(const float* __restrict__ er,
                                                const float* __restrict__ ei) {
    extern __shared__ float sm[];
    float *Er = sm, *Ei = Er+64*RP, *Xr = Ei+64*RP, *Xi = Xr+64*RP;
    int pt = blockIdx.x, n = blockIdx.y, tid = threadIdx.x, hw0 = pt*64;
    for (int l = tid; l < 4096; l += 256) {
        int dd = l>>6, e = l&63;
        Er[dd*RP+e] = er[l]; Ei[dd*RP+e] = ei[l];
    }
    for (int l = tid; l < 4096; l += 256) {
        int dd = l>>6, p = l&63;
        int gi_ = (n*ND+dd)*NHW + hw0 + p;
        Xr[dd*RP+p] = g_c[gi_]; Xi[dd*RP+p] = g_d[gi_];
    }
    __syncthreads();
    int e0 = (tid>>4)*4, p0 = (tid&15)*4;
    u64 pr_[4][2] = {}, pi_[4][2] = {};
    for (int dd = 0; dd < 64; dd++) {
        u64 x0 = lds2(&Xr[dd*RP+p0]), x1 = lds2(&Xr[dd*RP+p0+2]);
        u64 y0 = lds2(&Xi[dd*RP+p0]), y1 = lds2(&Xi[dd*RP+p0+2]);
        float2 ea = *(const float2*)&Er[dd*RP+e0], eb = *(const float2*)&Er[dd*RP+e0+2];
        float2 qa = *(const float2*)&Ei[dd*RP+e0], qb = *(const float2*)&Ei[dd*RP+e0+2];
        float ers[4] = {ea.x, ea.y, eb.x, eb.y};
        float eis[4] = {qa.x, qa.y, qb.x, qb.y};
        #pragma unroll
        for (int i = 0; i < 4; i++) {
            u64 ber = bc(ers[i]), bei = bc(eis[i]), bnei = bc(-eis[i]);
            fma2(pr_[i][0], x0, ber); fma2(pr_[i][0], y0, bnei);
            fma2(pr_[i][1], x1, ber); fma2(pr_[i][1], y1, bnei);
            fma2(pi_[i][0], x0, bei); fma2(pi_[i][0], y0, ber);
            fma2(pi_[i][1], x1, bei); fma2(pi_[i][1], y1, ber);
        }
    }
    #pragma unroll
    for (int i = 0; i < 4; i++)
        for (int jp = 0; jp < 2; jp++) {
            int gi_ = (n*ND + e0+i)*NHW + hw0 + p0 + 2*jp;
            *(float2*)&g_c[gi_] = up(pr_[i][jp]);
            *(float2*)&g_d[gi_] = up(pi_[i][jp]);
        }
}

// ---------- diagonal ZOH recurrence over t, in place ----------
__global__ void k_rec(const float* __restrict__ dt, const float* __restrict__ lr_,
                      const float* __restrict__ li_) {
    int idx = blockIdx.x*blockDim.x + threadIdx.x;
    if (idx >= NBB*ND*NHW) return;
    int hw = idx & (NHW-1);
    int e  = (idx>>12) & 63;
    int b  = idx>>18;
    float dtb = dt[b], lr = lr_[e], li = li_[e];
    float ex = expf(lr*dtb);
    float sn, cs; sincosf(li*dtb, &sn, &cs);
    float dr = ex*cs, di = ex*sn;
    float nr = dr-1.f, ni = di;
    float den = 1.f/(lr*lr + li*li);
    float fr_ = (nr*lr + ni*li)*den;
    float fi_ = (ni*lr - nr*li)*den;
    float hr = 0.f, hi = 0.f;
    #pragma unroll 1
    for (int t = 0; t < NTT; t++) {
        int gi_ = ((b*NTT+t)*ND + e)*NHW + hw;
        float ur = g_c[gi_], ui = g_d[gi_];
        float nhr = hr*dr - hi*di + ur*fr_ - ui*fi_;
        float nhi = hr*di + hi*dr + ur*fi_ + ui*fr_;
        hr = nhr; hi = nhi;
        g_c[gi_] = hr; g_d[gi_] = hi;
    }
}

// ---------- decode real part + residual -> g_c ----------
__global__ __launch_bounds__(256, 3) void k_dec(const float* __restrict__ dmr,
                                                const float* __restrict__ dmi) {
    extern __shared__ float sm[];
    float *Dr = sm, *Di = Dr+64*RP, *Hr = Di+64*RP, *Hi = Hr+64*RP;
    int pt = blockIdx.x, n = blockIdx.y, tid = threadIdx.x, hw0 = pt*64;
    for (int l = tid; l < 4096; l += 256) {
        int e = l>>6, c = l&63;
        Dr[e*RP+c] = dmr[l]; Di[e*RP+c] = dmi[l];
    }
    for (int l = tid; l < 4096; l += 256) {
        int e = l>>6, p = l&63;
        int gi_ = (n*ND+e)*NHW + hw0 + p;
        Hr[e*RP+p] = g_c[gi_]; Hi[e*RP+p] = g_d[gi_];
    }
    __syncthreads();
    int c0 = (tid>>4)*4, p0 = (tid&15)*4;
    u64 accp[4][2] = {};
    for (int e = 0; e < 64; e++) {
        u64 x0 = lds2(&Hr[e*RP+p0]), x1 = lds2(&Hr[e*RP+p0+2]);
        u64 y0 = lds2(&Hi[e*RP+p0]), y1 = lds2(&Hi[e*RP+p0+2]);
        float2 da = *(const float2*)&Dr[e*RP+c0], db = *(const float2*)&Dr[e*RP+c0+2];
        float2 qa = *(const float2*)&Di[e*RP+c0], qb = *(const float2*)&Di[e*RP+c0+2];
        float drs[4] = {da.x, da.y, db.x, db.y};
        float dis[4] = {qa.x, qa.y, qb.x, qb.y};
        #pragma unroll
        for (int i = 0; i < 4; i++) {
            u64 bdr = bc(drs[i]), bnd = bc(-dis[i]);
            fma2(accp[i][0], x0, bdr); fma2(accp[i][0], y0, bnd);
            fma2(accp[i][1], x1, bdr); fma2(accp[i][1], y1, bnd);
        }
    }
    #pragma unroll
    for (int i = 0; i < 4; i++)
        for (int jp = 0; jp < 2; jp++) {
            int gi_ = (n*ND + c0+i)*NHW + hw0 + p0 + 2*jp;
            float2 v = up(accp[i][jp]);
            float2 rs = *(const float2*)&g_a[gi_];
            v.x += rs.x; v.y += rs.y;
            *(float2*)&g_c[gi_] = v;
        }
}

// ---------- fast gelu ----------
__device__ __forceinline__ float gelu_f(float x) {
    float u = 0.7978845608028654f*(x + 0.044715f*x*x*x);
    return x * (1.f - __fdividef(1.f, __expf(2.f*u) + 1.f));
}

// ---------- fused MLP 128 -> 512(gelu) -> 128 + residual, f chunked by 32 ----------
#define MLP_SM ((128*66 + 32*66 + 128*34)*4)
__global__ __launch_bounds__(256, 3) void k_mlp(const float* __restrict__ w1,
                                                const float* __restrict__ b1,
                                                const float* __restrict__ w2,
                                                const float* __restrict__ b2,
                                                float* __restrict__ out) {
    extern __shared__ float sm[];
    float *Xs = sm;                // [128][66]
    float *Hs = Xs + 128*66;       // [32][66]
    float *Ws = Hs + 32*66;        // w1 chunk [128][34] or w2 chunk [32][130]
    int pt = blockIdx.x, n = blockIdx.y, tid = threadIdx.x, hw0 = pt*64;
    for (int l = tid; l < 128*64; l += 256) {
        int c = l>>6, p = l&63;
        float v = (c < 64) ? g_c[(n*ND+c)*NHW + hw0 + p]
                           : g_b[(n*ND+c-64)*NHW + hw0 + p];
        Xs[c*66+p] = v;
    }
    // gemm1 tile: 2f x 4p (16 fg x 16 pg); gemm2 tile: 8c x 4p
    int fg = (tid>>4)*2, p0 = (tid&15)*4;
    int c8 = (tid>>4)*8;
    u64 accp[4][4];
    #pragma unroll
    for (int i = 0; i < 4; i++)
        for (int j = 0; j < 4; j++) accp[i][j] = 0ull;
    for (int fc = 0; fc < 16; fc++) {
        __syncthreads();   // prior gemm2 done with Ws/Hs; Xs ready on first iter
        for (int l = tid; l < 128*32; l += 256) {
            int c = l>>5, f = l&31;
            Ws[c*34+f] = w1[c*512 + fc*32 + f];
        }
        __syncthreads();
        u64 a2p[4] = {};
        for (int c = 0; c < 128; c++) {
            float2 x01 = *(const float2*)&Xs[c*66+p0];
            float2 x23 = *(const float2*)&Xs[c*66+p0+2];
            u64 w01 = lds2(&Ws[c*34+fg]);
            fma2(a2p[0], w01, bc(x01.x)); fma2(a2p[1], w01, bc(x01.y));
            fma2(a2p[2], w01, bc(x23.x)); fma2(a2p[3], w01, bc(x23.y));
        }
        __syncthreads();   // gemm1 done reading Ws
        {
            int fA = fg, fB = fg + 1;
            float biasA = b1[fc*32 + fA], biasB = b1[fc*32 + fB];
            #pragma unroll
            for (int j = 0; j < 4; j++) {
                float2 v = up(a2p[j]);
                Hs[fA*66 + p0+j] = gelu_f(v.x + biasA);
                Hs[fB*66 + p0+j] = gelu_f(v.y + biasB);
            }
        }
        for (int l = tid; l < 32*128; l += 256) {
            int f = l>>7, c = l&127;
            Ws[f*130+c] = w2[(fc*32+f)*128 + c];
        }
        __syncthreads();   // Hs + w2 chunk ready
        for (int f = 0; f < 32; f++) {
            float2 h01 = *(const float2*)&Hs[f*66+p0];
            float2 h23 = *(const float2*)&Hs[f*66+p0+2];
            u64 bh[4] = {bc(h01.x), bc(h01.y), bc(h23.x), bc(h23.y)};
            const u64* wp = (const u64*)&Ws[f*130+c8];
            #pragma unroll
            for (int ip = 0; ip < 4; ip++) {
                u64 wv = wp[ip];
                fma2(accp[ip][0], wv, bh[0]); fma2(accp[ip][1], wv, bh[1]);
                fma2(accp[ip][2], wv, bh[2]); fma2(accp[ip][3], wv, bh[3]);
            }
        }
    }
    #pragma unroll
    for (int ip = 0; ip < 4; ip++) {
        int cA = c8 + 2*ip, cB = cA + 1;
        float bA = b2[cA], bB = b2[cB];
        #pragma unroll
        for (int j = 0; j < 4; j++) {
            float2 v = up(accp[ip][j]);
            int p = p0 + j;
            float resA = (cA < 64) ? g_c[(n*ND+cA)*NHW + hw0 + p]
                                   : g_b[(n*ND+cA-64)*NHW + hw0 + p];
            float resB = (cB < 64) ? g_c[(n*ND+cB)*NHW + hw0 + p]
                                   : g_b[(n*ND+cB-64)*NHW + hw0 + p];
            out[((size_t)n*ND2 + cA)*NHW + hw0 + p] = v.x + bA + resA;
            out[((size_t)n*ND2 + cB)*NHW + hw0 + p] = v.y + bB + resB;
        }
    }
}

extern "C" void kernel_launch(void* const* d_in, const int* in_sizes, int n_in,
                              void* d_out, int out_size) {
    const float* xr   = (const float*)d_in[0];
    const float* xi   = (const float*)d_in[1];
    const float* dt   = (const float*)d_in[2];
    const float* lsg  = (const float*)d_in[3];
    const float* lsb  = (const float*)d_in[4];
    const float* cw   = (const float*)d_in[5];
    const float* cb   = (const float*)d_in[6];
    const float* swr  = (const float*)d_in[7];
    const float* swi  = (const float*)d_in[8];
    const float* gate = (const float*)d_in[9];
    const float* ltg  = (const float*)d_in[10];
    const float* ltb  = (const float*)d_in[11];
    const float* lamr = (const float*)d_in[12];
    const float* lami = (const float*)d_in[13];
    const float* enr  = (const float*)d_in[14];
    const float* eni  = (const float*)d_in[15];
    const float* dcr  = (const float*)d_in[16];
    const float* dci  = (const float*)d_in[17];
    const float* w1   = (const float*)d_in[18];
    const float* b1   = (const float*)d_in[19];
    const float* w2   = (const float*)d_in[20];
    const float* b2   = (const float*)d_in[21];
    float* out = (float*)d_out;

    cudaFuncSetAttribute(k_conv, cudaFuncAttributeMaxDynamicSharedMemorySize, CONV_SM);
    cudaFuncSetAttribute(k_fft,  cudaFuncAttributeMaxDynamicSharedMemorySize, FFT_SM);
    cudaFuncSetAttribute(k_enc,  cudaFuncAttributeMaxDynamicSharedMemorySize, GE_SM);
    cudaFuncSetAttribute(k_dec,  cudaFuncAttributeMaxDynamicSharedMemorySize, GE_SM);
    cudaFuncSetAttribute(k_mlp,  cudaFuncAttributeMaxDynamicSharedMemorySize, MLP_SM);

    dim3 gHN(64, 64);
    k_init<<<(128*128*9 + 255)/256, 256>>>(cw);
    k_ln<0><<<gHN, dim3(64,4)>>>(xr, xi, lsg, lsb);
    k_conv<<<gHN, 256, CONV_SM>>>(cb);
    k_fft<<<gHN, 256, FFT_SM>>>(swr, swi, xr, xi, gate);
    k_ln<1><<<gHN, dim3(64,4)>>>(nullptr, nullptr, ltg, ltb);
    k_enc<<<gHN, 256, GE_SM>>>(enr, eni);
    k_rec<<<(NBB*ND*NHW)/256, 256>>>(dt, lamr, lami);
    k_dec<<<gHN, 256, GE_SM>>>(dcr, dci);
    k_mlp<<<gHN, 256, MLP_SM>>>(w1, b1, w2, b2, out);
}

// round 7
// speedup vs baseline: 1.0815x; 1.0815x over previous
#include <cuda_runtime.h>
#include <math.h>

#define ND 64
#define ND2 128
#define NHW 4096
#define NBT 64
#define NTT 16
#define NBB 4
#define NTOT (NBT*ND*NHW)
#define PADW 66
#define PLANEP (PADW*PADW)
#define RP 66

typedef unsigned long long u64;

__device__ float g_pad[(size_t)NBT*ND2*PLANEP];   // zero-init: borders stay 0 forever
__device__ float g_a[NTOT], g_b[NTOT], g_c[NTOT], g_d[NTOT];
__device__ float g_w[128*128*9];                  // conv weights transposed [ic*9+tap][oc]
__device__ float g_twr[4096], g_twi[4096];        // DFT twiddle table F[u][w], symmetric

// ---- f32x2 helpers ----
__device__ __forceinline__ u64 pk(float lo, float hi) {
    u64 r; asm("mov.b64 %0, {%1,%2};" : "=l"(r) : "f"(lo), "f"(hi)); return r;
}
__device__ __forceinline__ u64 bc(float v) { return pk(v, v); }
__device__ __forceinline__ void fma2(u64& d, u64 a, u64 b) {
    asm("fma.rn.f32x2 %0, %1, %2, %0;" : "+l"(d) : "l"(a), "l"(b));
}
__device__ __forceinline__ float2 up(u64 v) {
    float2 f; asm("mov.b64 {%0,%1}, %2;" : "=f"(f.x), "=f"(f.y) : "l"(v)); return f;
}
__device__ __forceinline__ u64 lds2(const float* p) { return *(const u64*)p; }
__device__ __forceinline__ u64 ldg2(const float* p) { return *(const u64*)p; }

// ---------- init: conv weight transpose + twiddle table ----------
__global__ void k_init(const float* __restrict__ cw) {
    int i = blockIdx.x*blockDim.x + threadIdx.x;
    if (i < 4096) {
        const float W64 = 6.28318530717958647692f/64.f;
        int u = i>>6, w = i&63, t = (u*w)&63;
        float sv, cv; sincosf(-W64*(float)t, &sv, &cv);
        g_twr[i] = cv; g_twi[i] = sv;
    }
    if (i < 128*128*9) {
        int oc = i / 1152, rem = i - oc*1152;
        g_w[rem*128 + oc] = cw[i];
    }
}

// ---------- spatial complex LayerNorm -> padded buffer ----------
__global__ void k_ln0(const float* __restrict__ xr, const float* __restrict__ xi,
                      const float* __restrict__ gam, const float* __restrict__ bet) {
    __shared__ float s[128][64];
    __shared__ float ps[4][64], pq[4][64], mb[64], rb[64];
    int h = blockIdx.x, n = blockIdx.y;
    int tx = threadIdx.x, ty = threadIdx.y;
    int base = n*(ND*NHW) + h*64 + tx;
    float sum = 0.f, sq = 0.f;
    for (int j = 0; j < 32; j++) {
        int c = ty*32 + j;
        float v = (c < 64) ? xr[base + c*NHW] : xi[base + (c-64)*NHW];
        s[c][tx] = v; sum += v; sq += v*v;
    }
    ps[ty][tx] = sum; pq[ty][tx] = sq;
    __syncthreads();
    if (ty == 0) {
        float S = ps[0][tx]+ps[1][tx]+ps[2][tx]+ps[3][tx];
        float Q = pq[0][tx]+pq[1][tx]+pq[2][tx]+pq[3][tx];
        float m = S*(1.f/128.f);
        mb[tx] = m; rb[tx] = rsqrtf(Q*(1.f/128.f) - m*m + 1e-5f);
    }
    __syncthreads();
    float m = mb[tx], r = rb[tx];
    for (int j = 0; j < 32; j++) {
        int c = ty*32 + j;
        float y = (s[c][tx] - m)*r*gam[c] + bet[c];
        g_pad[((size_t)(n*ND2 + c))*PLANEP + (h+1)*PADW + tx+1] = y;
    }
}

// ---------- direct 3x3 conv 128->128, f32x2, ic chunked by 16 (R5 shape) ----------
#define CONV_SM ((3*16*66 + 16*9*128)*4)
__global__ __launch_bounds__(256) void k_conv(const float* __restrict__ cb) {
    extern __shared__ float sm[];
    float* sin_ = sm;              // [3][16][66]
    float* sw   = sm + 3*16*66;    // [16*9][128]
    int h = blockIdx.x, n = blockIdx.y, tid = threadIdx.x;
    const float* src = g_pad + (size_t)n*ND2*PLANEP;
    int wg = tid & 15, og = tid >> 4, w0 = wg*4;
    u64 accp[4][4];
    #pragma unroll
    for (int a = 0; a < 4; a++)
        for (int b2 = 0; b2 < 4; b2++) accp[a][b2] = 0ull;
    for (int icc = 0; icc < 8; icc++) {
        __syncthreads();
        for (int l = tid; l < 3*16*66; l += 256) {
            int r = l/(16*66), rem = l - r*(16*66);
            int icl = rem/66, c = rem - icl*66;
            sin_[l] = src[(size_t)(icc*16+icl)*PLANEP + (h + r)*PADW + c];
        }
        for (int l = tid; l < 16*9*128; l += 256)
            sw[l] = g_w[icc*16*9*128 + l];
        __syncthreads();
        #pragma unroll 1
        for (int icl = 0; icl < 16; icl++) {
            float inv[3][6];
            #pragma unroll
            for (int r = 0; r < 3; r++) {
                float2 t0 = *(const float2*)&sin_[(r*16+icl)*66 + w0];
                float2 t1 = *(const float2*)&sin_[(r*16+icl)*66 + w0 + 2];
                float2 t2 = *(const float2*)&sin_[(r*16+icl)*66 + w0 + 4];
                inv[r][0]=t0.x; inv[r][1]=t0.y; inv[r][2]=t1.x;
                inv[r][3]=t1.y; inv[r][4]=t2.x; inv[r][5]=t2.y;
            }
            #pragma unroll
            for (int ky = 0; ky < 3; ky++)
                for (int kx = 0; kx < 3; kx++) {
                    int tap = ky*3 + kx;
                    u64 b0 = bc(inv[ky][kx]),   b1 = bc(inv[ky][kx+1]);
                    u64 b2 = bc(inv[ky][kx+2]), b3 = bc(inv[ky][kx+3]);
                    const u64* wp = (const u64*)&sw[(icl*9+tap)*128 + og*8];
                    #pragma unroll
                    for (int op = 0; op < 4; op++) {
                        u64 wv = wp[op];
                        fma2(accp[op][0], wv, b0);
                        fma2(accp[op][1], wv, b1);
                        fma2(accp[op][2], wv, b2);
                        fma2(accp[op][3], wv, b3);
                    }
                }
        }
    }
    int ob = n*(ND*NHW) + h*64 + w0;
    #pragma unroll
    for (int op = 0; op < 4; op++) {
        int oc0 = og*8 + 2*op;
        float bia0 = cb[oc0], bia1 = cb[oc0+1];
        #pragma unroll
        for (int xw = 0; xw < 4; xw++) {
            float2 v = up(accp[op][xw]);
            float v0 = v.x + bia0, v1 = v.y + bia1;
            if (oc0 < 64) { g_a[ob + oc0*NHW + xw] = v0; g_a[ob + (oc0+1)*NHW + xw] = v1; }
            else { g_b[ob + (oc0-64)*NHW + xw] = v0; g_b[ob + (oc0-63)*NHW + xw] = v1; }
        }
    }
}

// ---------- spectral IFFT2(FFT2(x)*W), twiddles from global, fused combine ----------
#define FFT_SM (4*64*RP*4)
__global__ __launch_bounds__(256, 3) void k_fft(const float* __restrict__ swr,
                                                const float* __restrict__ swi,
                                                const float* __restrict__ xin_r,
                                                const float* __restrict__ xin_i,
                                                const float* __restrict__ gate) {
    extern __shared__ float sm[];
    float *ar = sm, *ai = ar+64*RP, *br = ai+64*RP, *bi = br+64*RP;
    int d = blockIdx.x, n = blockIdx.y, tid = threadIdx.x;
    const float* pr0 = g_pad + ((size_t)(n*ND2 + d))*PLANEP;
    const float* pi0 = g_pad + ((size_t)(n*ND2 + 64 + d))*PLANEP;
    for (int l = tid; l < 4096; l += 256) {
        int hh = l>>6, ww = l&63;
        ar[hh*RP+ww] = pr0[(hh+1)*PADW + ww+1];
        ai[hh*RP+ww] = pi0[(hh+1)*PADW + ww+1];
    }
    __syncthreads();
    int r0 = (tid>>4)*4, c0 = (tid&15)*4;
    { // pass1
        u64 pr_[4][2] = {}, pi_[4][2] = {};
        for (int w = 0; w < 64; w++) {
            u64 g0 = ldg2(&g_twr[w*64+c0]), g1 = ldg2(&g_twr[w*64+c0+2]);
            u64 q0 = ldg2(&g_twi[w*64+c0]), q1 = ldg2(&g_twi[w*64+c0+2]);
            #pragma unroll
            for (int i = 0; i < 4; i++) {
                float xr1 = ar[(r0+i)*RP+w], xi1 = ai[(r0+i)*RP+w];
                u64 bxr = bc(xr1), bxi = bc(xi1), bnxi = bc(-xi1);
                fma2(pr_[i][0], bxr, g0); fma2(pr_[i][0], bnxi, q0);
                fma2(pr_[i][1], bxr, g1); fma2(pr_[i][1], bnxi, q1);
                fma2(pi_[i][0], bxr, q0); fma2(pi_[i][0], bxi, g0);
                fma2(pi_[i][1], bxr, q1); fma2(pi_[i][1], bxi, g1);
            }
        }
        #pragma unroll
        for (int i = 0; i < 4; i++) {
            *(float2*)&br[(r0+i)*RP+c0]   = up(pr_[i][0]);
            *(float2*)&br[(r0+i)*RP+c0+2] = up(pr_[i][1]);
            *(float2*)&bi[(r0+i)*RP+c0]   = up(pi_[i][0]);
            *(float2*)&bi[(r0+i)*RP+c0+2] = up(pi_[i][1]);
        }
    }
    __syncthreads();
    { // pass2
        u64 pr_[4][2] = {}, pi_[4][2] = {};
        for (int hs = 0; hs < 64; hs++) {
            u64 x0 = lds2(&br[hs*RP+c0]), x1 = lds2(&br[hs*RP+c0+2]);
            u64 y0 = lds2(&bi[hs*RP+c0]), y1 = lds2(&bi[hs*RP+c0+2]);
            float2 ga = *(const float2*)&g_twr[hs*64+r0], gb2 = *(const float2*)&g_twr[hs*64+r0+2];
            float2 qa = *(const float2*)&g_twi[hs*64+r0], qb = *(const float2*)&g_twi[hs*64+r0+2];
            float grs[4] = {ga.x, ga.y, gb2.x, gb2.y};
            float gis[4] = {qa.x, qa.y, qb.x, qb.y};
            #pragma unroll
            for (int i = 0; i < 4; i++) {
                u64 bgr = bc(grs[i]), bgi = bc(gis[i]), bngi = bc(-gis[i]);
                fma2(pr_[i][0], bgr, x0); fma2(pr_[i][0], bngi, y0);
                fma2(pr_[i][1], bgr, x1); fma2(pr_[i][1], bngi, y1);
                fma2(pi_[i][0], bgr, y0); fma2(pi_[i][0], bgi, x0);
                fma2(pi_[i][1], bgr, y1); fma2(pi_[i][1], bgi, x1);
            }
        }
        __syncthreads();
        #pragma unroll
        for (int i = 0; i < 4; i++) {
            *(float2*)&ar[(r0+i)*RP+c0]   = up(pr_[i][0]);
            *(float2*)&ar[(r0+i)*RP+c0+2] = up(pr_[i][1]);
            *(float2*)&ai[(r0+i)*RP+c0]   = up(pi_[i][0]);
            *(float2*)&ai[(r0+i)*RP+c0+2] = up(pi_[i][1]);
        }
    }
    __syncthreads();
    { // pointwise * spec_w[d]
        const float* wr2 = swr + d*NHW; const float* wi2 = swi + d*NHW;
        for (int l = tid; l < 4096; l += 256) {
            int u = l>>6, v = l&63;
            float zr = ar[u*RP+v], zi = ai[u*RP+v];
            float wr_ = wr2[l], wi_ = wi2[l];
            ar[u*RP+v] = zr*wr_ - zi*wi_;
            ai[u*RP+v] = zr*wi_ + zi*wr_;
        }
    }
    __syncthreads();
    { // pass3
        u64 pr_[4][2] = {}, pi_[4][2] = {};
        for (int us = 0; us < 64; us++) {
            u64 x0 = lds2(&ar[us*RP+c0]), x1 = lds2(&ar[us*RP+c0+2]);
            u64 y0 = lds2(&ai[us*RP+c0]), y1 = lds2(&ai[us*RP+c0+2]);
            float2 ga = *(const float2*)&g_twr[us*64+r0], gb2 = *(const float2*)&g_twr[us*64+r0+2];
            float2 qa = *(const float2*)&g_twi[us*64+r0], qb = *(const float2*)&g_twi[us*64+r0+2];
            float grs[4] = {ga.x, ga.y, gb2.x, gb2.y};
            float gis[4] = {qa.x, qa.y, qb.x, qb.y};
            #pragma unroll
            for (int i = 0; i < 4; i++) {
                u64 bgr = bc(grs[i]), bgi = bc(gis[i]), bngi = bc(-gis[i]);
                fma2(pr_[i][0], bgr, x0); fma2(pr_[i][0], bgi, y0);
                fma2(pr_[i][1], bgr, x1); fma2(pr_[i][1], bgi, y1);
                fma2(pi_[i][0], bgr, y0); fma2(pi_[i][0], bngi, x0);
                fma2(pi_[i][1], bgr, y1); fma2(pi_[i][1], bngi, x1);
            }
        }
        #pragma unroll
        for (int i = 0; i < 4; i++) {
            *(float2*)&br[(r0+i)*RP+c0]   = up(pr_[i][0]);
            *(float2*)&br[(r0+i)*RP+c0+2] = up(pr_[i][1]);
            *(float2*)&bi[(r0+i)*RP+c0]   = up(pi_[i][0]);
            *(float2*)&bi[(r0+i)*RP+c0+2] = up(pi_[i][1]);
        }
    }
    __syncthreads();
    { // pass4 + fused combine
        u64 pr_[4][2] = {}, pi_[4][2] = {};
        for (int vs = 0; vs < 64; vs++) {
            u64 g0 = ldg2(&g_twr[vs*64+c0]), g1 = ldg2(&g_twr[vs*64+c0+2]);
            u64 q0 = ldg2(&g_twi[vs*64+c0]), q1 = ldg2(&g_twi[vs*64+c0+2]);
            #pragma unroll
            for (int i = 0; i < 4; i++) {
                float xr1 = br[(r0+i)*RP+vs], xi1 = bi[(r0+i)*RP+vs];
                u64 bxr = bc(xr1), bxi = bc(xi1), bnxr = bc(-xr1);
                fma2(pr_[i][0], bxr, g0); fma2(pr_[i][0], bxi, q0);
                fma2(pr_[i][1], bxr, g1); fma2(pr_[i][1], bxi, q1);
                fma2(pi_[i][0], bxi, g0); fma2(pi_[i][0], bnxr, q0);
                fma2(pi_[i][1], bxi, g1); fma2(pi_[i][1], bnxr, q1);
            }
        }
        const float sc = 1.f/4096.f;
        float g = gate[0], omg = 1.f - g;
        int base = n*ND*NHW + d*NHW;
        #pragma unroll
        for (int i = 0; i < 4; i++)
            for (int jp = 0; jp < 2; jp++) {
                int idx = base + (r0+i)*64 + c0 + 2*jp;
                float2 sr = up(pr_[i][jp]);
                float2 si = up(pi_[i][jp]);
                float2 clr = *(const float2*)&g_a[idx];
                float2 cli = *(const float2*)&g_b[idx];
                float2 inr = *(const float2*)&xin_r[idx];
                float2 ini = *(const float2*)&xin_i[idx];
                float2 orr, oii;
                orr.x = g*clr.x + omg*sr.x*sc + inr.x;
                orr.y = g*clr.y + omg*sr.y*sc + inr.y;
                oii.x = g*cli.x + omg*si.x*sc + ini.x;
                oii.y = g*cli.y + omg*si.y*sc + ini.y;
                *(float2*)&g_a[idx] = orr;
                *(float2*)&g_b[idx] = oii;
            }
    }
}

// ---------- fused temporal-LN + complex encode GEMM: g_a/g_b -> g_c/g_d ----------
#define GE_SM (4*64*RP*4)
__global__ __launch_bounds__(256, 3) void k_enc(const float* __restrict__ er,
                                                const float* __restrict__ ei,
                                                const float* __restrict__ gam,
                                                const float* __restrict__ bet) {
    extern __shared__ float sm[];
    float *Er = sm, *Ei = Er+64*RP, *Xr = Ei+64*RP, *Xi = Xr+64*RP;
    __shared__ float ps[4][64], pq[4][64], mb[64], rb[64];
    int pt = blockIdx.x, n = blockIdx.y, tid = threadIdx.x, hw0 = pt*64;
    for (int l = tid; l < 4096; l += 256) {
        int dd = l>>6, e = l&63;
        Er[dd*RP+e] = er[l]; Ei[dd*RP+e] = ei[l];
    }
    // load x1 (g_a/g_b) + accumulate LN stats; each thread owns position p=tid&63
    float sum = 0.f, sq = 0.f;
    for (int l = tid; l < 4096; l += 256) {
        int dd = l>>6, p = l&63;
        int gi_ = (n*ND+dd)*NHW + hw0 + p;
        float vr = g_a[gi_], vi = g_b[gi_];
        Xr[dd*RP+p] = vr; Xi[dd*RP+p] = vi;
        sum += vr + vi; sq += vr*vr + vi*vi;
    }
    ps[tid>>6][tid&63] = sum; pq[tid>>6][tid&63] = sq;
    __syncthreads();
    if (tid < 64) {
        float S = ps[0][tid]+ps[1][tid]+ps[2][tid]+ps[3][tid];
        float Q = pq[0][tid]+pq[1][tid]+pq[2][tid]+pq[3][tid];
        float m = S*(1.f/128.f);
        mb[tid] = m; rb[tid] = rsqrtf(Q*(1.f/128.f) - m*m + 1e-5f);
    }
    __syncthreads();
    {
        float m = mb[tid&63], r = rb[tid&63];
        for (int l = tid; l < 4096; l += 256) {
            int dd = l>>6, p = l&63;
            Xr[dd*RP+p] = (Xr[dd*RP+p] - m)*r*gam[dd]    + bet[dd];
            Xi[dd*RP+p] = (Xi[dd*RP+p] - m)*r*gam[dd+64] + bet[dd+64];
        }
    }
    __syncthreads();
    int e0 = (tid>>4)*4, p0 = (tid&15)*4;
    u64 pr_[4][2] = {}, pi_[4][2] = {};
    for (int dd = 0; dd < 64; dd++) {
        u64 x0 = lds2(&Xr[dd*RP+p0]), x1 = lds2(&Xr[dd*RP+p0+2]);
        u64 y0 = lds2(&Xi[dd*RP+p0]), y1 = lds2(&Xi[dd*RP+p0+2]);
        float2 ea = *(const float2*)&Er[dd*RP+e0], eb = *(const float2*)&Er[dd*RP+e0+2];
        float2 qa = *(const float2*)&Ei[dd*RP+e0], qb = *(const float2*)&Ei[dd*RP+e0+2];
        float ers[4] = {ea.x, ea.y, eb.x, eb.y};
        float eis[4] = {qa.x, qa.y, qb.x, qb.y};
        #pragma unroll
        for (int i = 0; i < 4; i++) {
            u64 ber = bc(ers[i]), bei = bc(eis[i]), bnei = bc(-eis[i]);
            fma2(pr_[i][0], x0, ber); fma2(pr_[i][0], y0, bnei);
            fma2(pr_[i][1], x1, ber); fma2(pr_[i][1], y1, bnei);
            fma2(pi_[i][0], x0, bei); fma2(pi_[i][0], y0, ber);
            fma2(pi_[i][1], x1, bei); fma2(pi_[i][1], y1, ber);
        }
    }
    #pragma unroll
    for (int i = 0; i < 4; i++)
        for (int jp = 0; jp < 2; jp++) {
            int gi_ = (n*ND + e0+i)*NHW + hw0 + p0 + 2*jp;
            *(float2*)&g_c[gi_] = up(pr_[i][jp]);
            *(float2*)&g_d[gi_] = up(pi_[i][jp]);
        }
}

// ---------- diagonal ZOH recurrence over t: batched loads, in place ----------
__global__ void k_rec(const float* __restrict__ dt, const float* __restrict__ lr_,
                      const float* __restrict__ li_) {
    int idx = blockIdx.x*blockDim.x + threadIdx.x;
    if (idx >= NBB*ND*NHW) return;
    int hw = idx & (NHW-1);
    int e  = (idx>>12) & 63;
    int b  = idx>>18;
    float dtb = dt[b], lr = lr_[e], li = li_[e];
    float ex = expf(lr*dtb);
    float sn, cs; sincosf(li*dtb, &sn, &cs);
    float dr = ex*cs, di = ex*sn;
    float nr = dr-1.f, ni = di;
    float den = 1.f/(lr*lr + li*li);
    float fr_ = (nr*lr + ni*li)*den;
    float fi_ = (ni*lr - nr*li)*den;
    int gi0 = (b*NTT*ND + e)*NHW + hw;
    float ur[NTT], ui_[NTT];
    #pragma unroll
    for (int t = 0; t < NTT; t++) {
        ur[t]  = g_c[gi0 + t*(ND*NHW)];
        ui_[t] = g_d[gi0 + t*(ND*NHW)];
    }
    float hr = 0.f, hi = 0.f;
    #pragma unroll
    for (int t = 0; t < NTT; t++) {
        float nhr = hr*dr - hi*di + ur[t]*fr_ - ui_[t]*fi_;
        float nhi = hr*di + hi*dr + ur[t]*fi_ + ui_[t]*fr_;
        hr = nhr; hi = nhi;
        ur[t] = hr; ui_[t] = hi;
    }
    #pragma unroll
    for (int t = 0; t < NTT; t++) {
        g_c[gi0 + t*(ND*NHW)] = ur[t];
        g_d[gi0 + t*(ND*NHW)] = ui_[t];
    }
}

// ---------- decode real part + residual -> g_c ----------
__global__ __launch_bounds__(256, 3) void k_dec(const float* __restrict__ dmr,
                                                const float* __restrict__ dmi) {
    extern __shared__ float sm[];
    float *Dr = sm, *Di = Dr+64*RP, *Hr = Di+64*RP, *Hi = Hr+64*RP;
    int pt = blockIdx.x, n = blockIdx.y, tid = threadIdx.x, hw0 = pt*64;
    for (int l = tid; l < 4096; l += 256) {
        int e = l>>6, c = l&63;
        Dr[e*RP+c] = dmr[l]; Di[e*RP+c] = dmi[l];
    }
    for (int l = tid; l < 4096; l += 256) {
        int e = l>>6, p = l&63;
        int gi_ = (n*ND+e)*NHW + hw0 + p;
        Hr[e*RP+p] = g_c[gi_]; Hi[e*RP+p] = g_d[gi_];
    }
    __syncthreads();
    int c0 = (tid>>4)*4, p0 = (tid&15)*4;
    u64 accp[4][2] = {};
    for (int e = 0; e < 64; e++) {
        u64 x0 = lds2(&Hr[e*RP+p0]), x1 = lds2(&Hr[e*RP+p0+2]);
        u64 y0 = lds2(&Hi[e*RP+p0]), y1 = lds2(&Hi[e*RP+p0+2]);
        float2 da = *(const float2*)&Dr[e*RP+c0], db = *(const float2*)&Dr[e*RP+c0+2];
        float2 qa = *(const float2*)&Di[e*RP+c0], qb = *(const float2*)&Di[e*RP+c0+2];
        float drs[4] = {da.x, da.y, db.x, db.y};
        float dis[4] = {qa.x, qa.y, qb.x, qb.y};
        #pragma unroll
        for (int i = 0; i < 4; i++) {
            u64 bdr = bc(drs[i]), bnd = bc(-dis[i]);
            fma2(accp[i][0], x0, bdr); fma2(accp[i][0], y0, bnd);
            fma2(accp[i][1], x1, bdr); fma2(accp[i][1], y1, bnd);
        }
    }
    #pragma unroll
    for (int i = 0; i < 4; i++)
        for (int jp = 0; jp < 2; jp++) {
            int gi_ = (n*ND + c0+i)*NHW + hw0 + p0 + 2*jp;
            float2 v = up(accp[i][jp]);
            float2 rs = *(const float2*)&g_a[gi_];
            v.x += rs.x; v.y += rs.y;
            *(float2*)&g_c[gi_] = v;
        }
}

// ---------- fast gelu ----------
__device__ __forceinline__ float gelu_f(float x) {
    float u = 0.7978845608028654f*(x + 0.044715f*x*x*x);
    return x * (1.f - __fdividef(1.f, __expf(2.f*u) + 1.f));
}

// ---------- fused MLP 128 -> 512(gelu) -> 128 + residual, f chunked by 64 (R5) ----------
#define MLP_SM ((128*66 + 64*66 + 8448)*4)
__global__ __launch_bounds__(256) void k_mlp(const float* __restrict__ w1,
                                             const float* __restrict__ b1,
                                             const float* __restrict__ w2,
                                             const float* __restrict__ b2,
                                             float* __restrict__ out) {
    extern __shared__ float sm[];
    float *Xs = sm;                // [128][66]
    float *Hs = Xs + 128*66;       // [64][66]
    float *Ws = Hs + 64*66;        // w1 chunk [128][66] or w2 chunk [64][130]
    int pt = blockIdx.x, n = blockIdx.y, tid = threadIdx.x, hw0 = pt*64;
    for (int l = tid; l < 128*64; l += 256) {
        int c = l>>6, p = l&63;
        float v = (c < 64) ? g_c[(n*ND+c)*NHW + hw0 + p]
                           : g_b[(n*ND+c-64)*NHW + hw0 + p];
        Xs[c*66+p] = v;
    }
    int fg = (tid>>4)*4, p0 = (tid&15)*4;
    int c8 = (tid>>4)*8;
    u64 accp[4][4];
    #pragma unroll
    for (int i = 0; i < 4; i++)
        for (int j = 0; j < 4; j++) accp[i][j] = 0ull;
    for (int fc = 0; fc < 8; fc++) {
        __syncthreads();
        for (int l = tid; l < 128*64; l += 256) {
            int c = l>>6, f = l&63;
            Ws[c*66+f] = w1[c*512 + fc*64 + f];
        }
        __syncthreads();
        u64 a2p[2][4];
        #pragma unroll
        for (int i = 0; i < 2; i++)
            for (int j = 0; j < 4; j++) a2p[i][j] = 0ull;
        for (int c = 0; c < 128; c++) {
            float2 x01 = *(const float2*)&Xs[c*66+p0];
            float2 x23 = *(const float2*)&Xs[c*66+p0+2];
            u64 bx[4] = {bc(x01.x), bc(x01.y), bc(x23.x), bc(x23.y)};
            u64 w01 = lds2(&Ws[c*66+fg]), w23 = lds2(&Ws[c*66+fg+2]);
            fma2(a2p[0][0], w01, bx[0]); fma2(a2p[0][1], w01, bx[1]);
            fma2(a2p[0][2], w01, bx[2]); fma2(a2p[0][3], w01, bx[3]);
            fma2(a2p[1][0], w23, bx[0]); fma2(a2p[1][1], w23, bx[1]);
            fma2(a2p[1][2], w23, bx[2]); fma2(a2p[1][3], w23, bx[3]);
        }
        __syncthreads();
        #pragma unroll
        for (int ip = 0; ip < 2; ip++) {
            int fA = fg + 2*ip, fB = fA + 1;
            float biasA = b1[fc*64 + fA], biasB = b1[fc*64 + fB];
            float2 v0 = up(a2p[ip][0]), v1 = up(a2p[ip][1]);
            float2 v2 = up(a2p[ip][2]), v3 = up(a2p[ip][3]);
            Hs[fA*66 + p0]   = gelu_f(v0.x + biasA);
            Hs[fA*66 + p0+1] = gelu_f(v1.x + biasA);
            Hs[fA*66 + p0+2] = gelu_f(v2.x + biasA);
            Hs[fA*66 + p0+3] = gelu_f(v3.x + biasA);
            Hs[fB*66 + p0]   = gelu_f(v0.y + biasB);
            Hs[fB*66 + p0+1] = gelu_f(v1.y + biasB);
            Hs[fB*66 + p0+2] = gelu_f(v2.y + biasB);
            Hs[fB*66 + p0+3] = gelu_f(v3.y + biasB);
        }
        for (int l = tid; l < 64*128; l += 256) {
            int f = l>>7, c = l&127;
            Ws[f*130+c] = w2[(fc*64+f)*128 + c];
        }
        __syncthreads();
        for (int f = 0; f < 64; f++) {
            float2 h01 = *(const float2*)&Hs[f*66+p0];
            float2 h23 = *(const float2*)&Hs[f*66+p0+2];
            u64 bh[4] = {bc(h01.x), bc(h01.y), bc(h23.x), bc(h23.y)};
            const u64* wp = (const u64*)&Ws[f*130+c8];
            #pragma unroll
            for (int ip = 0; ip < 4; ip++) {
                u64 wv = wp[ip];
                fma2(accp[ip][0], wv, bh[0]); fma2(accp[ip][1], wv, bh[1]);
                fma2(accp[ip][2], wv, bh[2]); fma2(accp[ip][3], wv, bh[3]);
            }
        }
    }
    #pragma unroll
    for (int ip = 0; ip < 4; ip++) {
        int cA = c8 + 2*ip, cB = cA + 1;
        float bA = b2[cA], bB = b2[cB];
        #pragma unroll
        for (int j = 0; j < 4; j++) {
            float2 v = up(accp[ip][j]);
            int p = p0 + j;
            float resA = (cA < 64) ? g_c[(n*ND+cA)*NHW + hw0 + p]
                                   : g_b[(n*ND+cA-64)*NHW + hw0 + p];
            float resB = (cB < 64) ? g_c[(n*ND+cB)*NHW + hw0 + p]
                                   : g_b[(n*ND+cB-64)*NHW + hw0 + p];
            out[((size_t)n*ND2 + cA)*NHW + hw0 + p] = v.x + bA + resA;
            out[((size_t)n*ND2 + cB)*NHW + hw0 + p] = v.y + bB + resB;
        }
    }
}

extern "C" void kernel_launch(void* const* d_in, const int* in_sizes, int n_in,
                              void* d_out, int out_size) {
    const float* xr   = (const float*)d_in[0];
    const float* xi   = (const float*)d_in[1];
    const float* dt   = (const float*)d_in[2];
    const float* lsg  = (const float*)d_in[3];
    const float* lsb  = (const float*)d_in[4];
    const float* cw   = (const float*)d_in[5];
    const float* cb   = (const float*)d_in[6];
    const float* swr  = (const float*)d_in[7];
    const float* swi  = (const float*)d_in[8];
    const float* gate = (const float*)d_in[9];
    const float* ltg  = (const float*)d_in[10];
    const float* ltb  = (const float*)d_in[11];
    const float* lamr = (const float*)d_in[12];
    const float* lami = (const float*)d_in[13];
    const float* enr  = (const float*)d_in[14];
    const float* eni  = (const float*)d_in[15];
    const float* dcr  = (const float*)d_in[16];
    const float* dci  = (const float*)d_in[17];
    const float* w1   = (const float*)d_in[18];
    const float* b1   = (const float*)d_in[19];
    const float* w2   = (const float*)d_in[20];
    const float* b2   = (const float*)d_in[21];
    float* out = (float*)d_out;

    cudaFuncSetAttribute(k_conv, cudaFuncAttributeMaxDynamicSharedMemorySize, CONV_SM);
    cudaFuncSetAttribute(k_fft,  cudaFuncAttributeMaxDynamicSharedMemorySize, FFT_SM);
    cudaFuncSetAttribute(k_enc,  cudaFuncAttributeMaxDynamicSharedMemorySize, GE_SM);
    cudaFuncSetAttribute(k_dec,  cudaFuncAttributeMaxDynamicSharedMemorySize, GE_SM);
    cudaFuncSetAttribute(k_mlp,  cudaFuncAttributeMaxDynamicSharedMemorySize, MLP_SM);

    dim3 gHN(64, 64);
    k_init<<<(128*128*9 + 255)/256, 256>>>(cw);
    k_ln0<<<gHN, dim3(64,4)>>>(xr, xi, lsg, lsb);
    k_conv<<<gHN, 256, CONV_SM>>>(cb);
    k_fft<<<gHN, 256, FFT_SM>>>(swr, swi, xr, xi, gate);
    k_enc<<<gHN, 256, GE_SM>>>(enr, eni, ltg, ltb);
    k_rec<<<(NBB*ND*NHW)/256, 256>>>(dt, lamr, lami);
    k_dec<<<gHN, 256, GE_SM>>>(dcr, dci);
    k_mlp<<<gHN, 256, MLP_SM>>>(w1, b1, w2, b2, out);
}

// round 9
// speedup vs baseline: 1.1132x; 1.0293x over previous
#include <cuda_runtime.h>
#include <math.h>

#define ND 64
#define ND2 128
#define NHW 4096
#define NBT 64
#define NTT 16
#define NBB 4
#define NTOT (NBT*ND*NHW)
#define PADW 66
#define PLANEP (PADW*PADW)
#define RP 66

typedef unsigned long long u64;

__device__ float g_pad[(size_t)NBT*ND2*PLANEP];   // zero-init: borders stay 0 forever
__device__ float g_a[NTOT], g_b[NTOT], g_c[NTOT], g_d[NTOT];
__device__ float g_w[128*128*9];                  // conv weights transposed [ic*9+tap][oc]
__device__ float g_twr[4096], g_twi[4096];        // DFT twiddle table F[u][w], symmetric

// ---- f32x2 helpers ----
__device__ __forceinline__ u64 pk(float lo, float hi) {
    u64 r; asm("mov.b64 %0, {%1,%2};" : "=l"(r) : "f"(lo), "f"(hi)); return r;
}
__device__ __forceinline__ u64 bc(float v) { return pk(v, v); }
__device__ __forceinline__ void fma2(u64& d, u64 a, u64 b) {
    asm("fma.rn.f32x2 %0, %1, %2, %0;" : "+l"(d) : "l"(a), "l"(b));
}
__device__ __forceinline__ float2 up(u64 v) {
    float2 f; asm("mov.b64 {%0,%1}, %2;" : "=f"(f.x), "=f"(f.y) : "l"(v)); return f;
}
__device__ __forceinline__ u64 lds2(const float* p) { return *(const u64*)p; }
__device__ __forceinline__ u64 ldg2(const float* p) { return *(const u64*)p; }

// ---------- init: conv weight transpose + twiddle table ----------
__global__ void k_init(const float* __restrict__ cw) {
    int i = blockIdx.x*blockDim.x + threadIdx.x;
    if (i < 4096) {
        const float W64 = 6.28318530717958647692f/64.f;
        int u = i>>6, w = i&63, t = (u*w)&63;
        float sv, cv; sincosf(-W64*(float)t, &sv, &cv);
        g_twr[i] = cv; g_twi[i] = sv;
    }
    if (i < 128*128*9) {
        int oc = i / 1152, rem = i - oc*1152;
        g_w[rem*128 + oc] = cw[i];
    }
}

// ---------- spatial complex LayerNorm -> padded buffer ----------
__global__ void k_ln0(const float* __restrict__ xr, const float* __restrict__ xi,
                      const float* __restrict__ gam, const float* __restrict__ bet) {
    __shared__ float s[128][64];
    __shared__ float ps[4][64], pq[4][64], mb[64], rb[64];
    int h = blockIdx.x, n = blockIdx.y;
    int tx = threadIdx.x, ty = threadIdx.y;
    int base = n*(ND*NHW) + h*64 + tx;
    float sum = 0.f, sq = 0.f;
    for (int j = 0; j < 32; j++) {
        int c = ty*32 + j;
        float v = (c < 64) ? xr[base + c*NHW] : xi[base + (c-64)*NHW];
        s[c][tx] = v; sum += v; sq += v*v;
    }
    ps[ty][tx] = sum; pq[ty][tx] = sq;
    __syncthreads();
    if (ty == 0) {
        float S = ps[0][tx]+ps[1][tx]+ps[2][tx]+ps[3][tx];
        float Q = pq[0][tx]+pq[1][tx]+pq[2][tx]+pq[3][tx];
        float m = S*(1.f/128.f);
        mb[tx] = m; rb[tx] = rsqrtf(Q*(1.f/128.f) - m*m + 1e-5f);
    }
    __syncthreads();
    float m = mb[tx], r = rb[tx];
    for (int j = 0; j < 32; j++) {
        int c = ty*32 + j;
        float y = (s[c][tx] - m)*r*gam[c] + bet[c];
        g_pad[((size_t)(n*ND2 + c))*PLANEP + (h+1)*PADW + tx+1] = y;
    }
}

// ---------- direct 3x3 conv 128->128, f32x2, ic chunked by 16 ----------
#define CONV_SM ((3*16*66 + 16*9*128)*4)
__global__ __launch_bounds__(256) void k_conv(const float* __restrict__ cb) {
    extern __shared__ float sm[];
    float* sin_ = sm;              // [3][16][66]
    float* sw   = sm + 3*16*66;    // [16*9][128]
    int h = blockIdx.x, n = blockIdx.y, tid = threadIdx.x;
    const float* src = g_pad + (size_t)n*ND2*PLANEP;
    int wg = tid & 15, og = tid >> 4, w0 = wg*4;
    u64 accp[4][4];
    #pragma unroll
    for (int a = 0; a < 4; a++)
        for (int b2 = 0; b2 < 4; b2++) accp[a][b2] = 0ull;
    for (int icc = 0; icc < 8; icc++) {
        __syncthreads();
        for (int l = tid; l < 3*16*66; l += 256) {
            int r = l/(16*66), rem = l - r*(16*66);
            int icl = rem/66, c = rem - icl*66;
            sin_[l] = src[(size_t)(icc*16+icl)*PLANEP + (h + r)*PADW + c];
        }
        for (int l = tid; l < 16*9*128; l += 256)
            sw[l] = g_w[icc*16*9*128 + l];
        __syncthreads();
        #pragma unroll 1
        for (int icl = 0; icl < 16; icl++) {
            float inv[3][6];
            #pragma unroll
            for (int r = 0; r < 3; r++) {
                float2 t0 = *(const float2*)&sin_[(r*16+icl)*66 + w0];
                float2 t1 = *(const float2*)&sin_[(r*16+icl)*66 + w0 + 2];
                float2 t2 = *(const float2*)&sin_[(r*16+icl)*66 + w0 + 4];
                inv[r][0]=t0.x; inv[r][1]=t0.y; inv[r][2]=t1.x;
                inv[r][3]=t1.y; inv[r][4]=t2.x; inv[r][5]=t2.y;
            }
            #pragma unroll
            for (int ky = 0; ky < 3; ky++)
                for (int kx = 0; kx < 3; kx++) {
                    int tap = ky*3 + kx;
                    u64 b0 = bc(inv[ky][kx]),   b1 = bc(inv[ky][kx+1]);
                    u64 b2 = bc(inv[ky][kx+2]), b3 = bc(inv[ky][kx+3]);
                    const u64* wp = (const u64*)&sw[(icl*9+tap)*128 + og*8];
                    #pragma unroll
                    for (int op = 0; op < 4; op++) {
                        u64 wv = wp[op];
                        fma2(accp[op][0], wv, b0);
                        fma2(accp[op][1], wv, b1);
                        fma2(accp[op][2], wv, b2);
                        fma2(accp[op][3], wv, b3);
                    }
                }
        }
    }
    int ob = n*(ND*NHW) + h*64 + w0;
    #pragma unroll
    for (int op = 0; op < 4; op++) {
        int oc0 = og*8 + 2*op;
        float bia0 = cb[oc0], bia1 = cb[oc0+1];
        float2 v0 = up(accp[op][0]), v1 = up(accp[op][1]);
        float2 v2 = up(accp[op][2]), v3 = up(accp[op][3]);
        float4 a4 = make_float4(v0.x+bia0, v1.x+bia0, v2.x+bia0, v3.x+bia0);
        float4 b4 = make_float4(v0.y+bia1, v1.y+bia1, v2.y+bia1, v3.y+bia1);
        if (oc0 < 64) {
            *(float4*)&g_a[ob + oc0*NHW]     = a4;
            *(float4*)&g_a[ob + (oc0+1)*NHW] = b4;
        } else {
            *(float4*)&g_b[ob + (oc0-64)*NHW] = a4;
            *(float4*)&g_b[ob + (oc0-63)*NHW] = b4;
        }
    }
}

// ---------- spectral IFFT2(FFT2(x)*W), twiddles from global, fused combine ----------
#define FFT_SM (4*64*RP*4)
__global__ __launch_bounds__(256, 3) void k_fft(const float* __restrict__ swr,
                                                const float* __restrict__ swi,
                                                const float* __restrict__ xin_r,
                                                const float* __restrict__ xin_i,
                                                const float* __restrict__ gate) {
    extern __shared__ float sm[];
    float *ar = sm, *ai = ar+64*RP, *br = ai+64*RP, *bi = br+64*RP;
    int d = blockIdx.x, n = blockIdx.y, tid = threadIdx.x;
    const float* pr0 = g_pad + ((size_t)(n*ND2 + d))*PLANEP;
    const float* pi0 = g_pad + ((size_t)(n*ND2 + 64 + d))*PLANEP;
    for (int l = tid; l < 4096; l += 256) {
        int hh = l>>6, ww = l&63;
        ar[hh*RP+ww] = pr0[(hh+1)*PADW + ww+1];
        ai[hh*RP+ww] = pi0[(hh+1)*PADW + ww+1];
    }
    __syncthreads();
    int r0 = (tid>>4)*4, c0 = (tid&15)*4;
    { // pass1
        u64 pr_[4][2] = {}, pi_[4][2] = {};
        for (int w = 0; w < 64; w++) {
            u64 g0 = ldg2(&g_twr[w*64+c0]), g1 = ldg2(&g_twr[w*64+c0+2]);
            u64 q0 = ldg2(&g_twi[w*64+c0]), q1 = ldg2(&g_twi[w*64+c0+2]);
            #pragma unroll
            for (int i = 0; i < 4; i++) {
                float xr1 = ar[(r0+i)*RP+w], xi1 = ai[(r0+i)*RP+w];
                u64 bxr = bc(xr1), bxi = bc(xi1), bnxi = bc(-xi1);
                fma2(pr_[i][0], bxr, g0); fma2(pr_[i][0], bnxi, q0);
                fma2(pr_[i][1], bxr, g1); fma2(pr_[i][1], bnxi, q1);
                fma2(pi_[i][0], bxr, q0); fma2(pi_[i][0], bxi, g0);
                fma2(pi_[i][1], bxr, q1); fma2(pi_[i][1], bxi, g1);
            }
        }
        #pragma unroll
        for (int i = 0; i < 4; i++) {
            *(float2*)&br[(r0+i)*RP+c0]   = up(pr_[i][0]);
            *(float2*)&br[(r0+i)*RP+c0+2] = up(pr_[i][1]);
            *(float2*)&bi[(r0+i)*RP+c0]   = up(pi_[i][0]);
            *(float2*)&bi[(r0+i)*RP+c0+2] = up(pi_[i][1]);
        }
    }
    __syncthreads();
    { // pass2
        u64 pr_[4][2] = {}, pi_[4][2] = {};
        for (int hs = 0; hs < 64; hs++) {
            u64 x0 = lds2(&br[hs*RP+c0]), x1 = lds2(&br[hs*RP+c0+2]);
            u64 y0 = lds2(&bi[hs*RP+c0]), y1 = lds2(&bi[hs*RP+c0+2]);
            float2 ga = *(const float2*)&g_twr[hs*64+r0], gb2 = *(const float2*)&g_twr[hs*64+r0+2];
            float2 qa = *(const float2*)&g_twi[hs*64+r0], qb = *(const float2*)&g_twi[hs*64+r0+2];
            float grs[4] = {ga.x, ga.y, gb2.x, gb2.y};
            float gis[4] = {qa.x, qa.y, qb.x, qb.y};
            #pragma unroll
            for (int i = 0; i < 4; i++) {
                u64 bgr = bc(grs[i]), bgi = bc(gis[i]), bngi = bc(-gis[i]);
                fma2(pr_[i][0], bgr, x0); fma2(pr_[i][0], bngi, y0);
                fma2(pr_[i][1], bgr, x1); fma2(pr_[i][1], bngi, y1);
                fma2(pi_[i][0], bgr, y0); fma2(pi_[i][0], bgi, x0);
                fma2(pi_[i][1], bgr, y1); fma2(pi_[i][1], bgi, x1);
            }
        }
        __syncthreads();
        #pragma unroll
        for (int i = 0; i < 4; i++) {
            *(float2*)&ar[(r0+i)*RP+c0]   = up(pr_[i][0]);
            *(float2*)&ar[(r0+i)*RP+c0+2] = up(pr_[i][1]);
            *(float2*)&ai[(r0+i)*RP+c0]   = up(pi_[i][0]);
            *(float2*)&ai[(r0+i)*RP+c0+2] = up(pi_[i][1]);
        }
    }
    __syncthreads();
    { // pointwise * spec_w[d]
        const float* wr2 = swr + d*NHW; const float* wi2 = swi + d*NHW;
        for (int l = tid; l < 4096; l += 256) {
            int u = l>>6, v = l&63;
            float zr = ar[u*RP+v], zi = ai[u*RP+v];
            float wr_ = wr2[l], wi_ = wi2[l];
            ar[u*RP+v] = zr*wr_ - zi*wi_;
            ai[u*RP+v] = zr*wi_ + zi*wr_;
        }
    }
    __syncthreads();
    { // pass3
        u64 pr_[4][2] = {}, pi_[4][2] = {};
        for (int us = 0; us < 64; us++) {
            u64 x0 = lds2(&ar[us*RP+c0]), x1 = lds2(&ar[us*RP+c0+2]);
            u64 y0 = lds2(&ai[us*RP+c0]), y1 = lds2(&ai[us*RP+c0+2]);
            float2 ga = *(const float2*)&g_twr[us*64+r0], gb2 = *(const float2*)&g_twr[us*64+r0+2];
            float2 qa = *(const float2*)&g_twi[us*64+r0], qb = *(const float2*)&g_twi[us*64+r0+2];
            float grs[4] = {ga.x, ga.y, gb2.x, gb2.y};
            float gis[4] = {qa.x, qa.y, qb.x, qb.y};
            #pragma unroll
            for (int i = 0; i < 4; i++) {
                u64 bgr = bc(grs[i]), bgi = bc(gis[i]), bngi = bc(-gis[i]);
                fma2(pr_[i][0], bgr, x0); fma2(pr_[i][0], bgi, y0);
                fma2(pr_[i][1], bgr, x1); fma2(pr_[i][1], bgi, y1);
                fma2(pi_[i][0], bgr, y0); fma2(pi_[i][0], bngi, x0);
                fma2(pi_[i][1], bgr, y1); fma2(pi_[i][1], bngi, x1);
            }
        }
        #pragma unroll
        for (int i = 0; i < 4; i++) {
            *(float2*)&br[(r0+i)*RP+c0]   = up(pr_[i][0]);
            *(float2*)&br[(r0+i)*RP+c0+2] = up(pr_[i][1]);
            *(float2*)&bi[(r0+i)*RP+c0]   = up(pi_[i][0]);
            *(float2*)&bi[(r0+i)*RP+c0+2] = up(pi_[i][1]);
        }
    }
    __syncthreads();
    { // pass4 + fused combine
        u64 pr_[4][2] = {}, pi_[4][2] = {};
        for (int vs = 0; vs < 64; vs++) {
            u64 g0 = ldg2(&g_twr[vs*64+c0]), g1 = ldg2(&g_twr[vs*64+c0+2]);
            u64 q0 = ldg2(&g_twi[vs*64+c0]), q1 = ldg2(&g_twi[vs*64+c0+2]);
            #pragma unroll
            for (int i = 0; i < 4; i++) {
                float xr1 = br[(r0+i)*RP+vs], xi1 = bi[(r0+i)*RP+vs];
                u64 bxr = bc(xr1), bxi = bc(xi1), bnxr = bc(-xr1);
                fma2(pr_[i][0], bxr, g0); fma2(pr_[i][0], bxi, q0);
                fma2(pr_[i][1], bxr, g1); fma2(pr_[i][1], bxi, q1);
                fma2(pi_[i][0], bxi, g0); fma2(pi_[i][0], bnxr, q0);
                fma2(pi_[i][1], bxi, g1); fma2(pi_[i][1], bnxr, q1);
            }
        }
        const float sc = 1.f/4096.f;
        float g = gate[0], omg = 1.f - g;
        int base = n*ND*NHW + d*NHW;
        #pragma unroll
        for (int i = 0; i < 4; i++)
            for (int jp = 0; jp < 2; jp++) {
                int idx = base + (r0+i)*64 + c0 + 2*jp;
                float2 sr = up(pr_[i][jp]);
                float2 si = up(pi_[i][jp]);
                float2 clr = *(const float2*)&g_a[idx];
                float2 cli = *(const float2*)&g_b[idx];
                float2 inr = *(const float2*)&xin_r[idx];
                float2 ini = *(const float2*)&xin_i[idx];
                float2 orr, oii;
                orr.x = g*clr.x + omg*sr.x*sc + inr.x;
                orr.y = g*clr.y + omg*sr.y*sc + inr.y;
                oii.x = g*cli.x + omg*si.x*sc + ini.x;
                oii.y = g*cli.y + omg*si.y*sc + ini.y;
                *(float2*)&g_a[idx] = orr;
                *(float2*)&g_b[idx] = oii;
            }
    }
}

// ---------- fused temporal branch: LN + encode + recurrence + decode + resid ----------
// block = (pt, b); loops t = 0..15 with per-thread register recurrence state.
#define TEMP_SM (6*64*RP*4)
__global__ __launch_bounds__(256, 2) void k_temporal(
        const float* __restrict__ er, const float* __restrict__ ei,
        const float* __restrict__ dmr, const float* __restrict__ dmi,
        const float* __restrict__ gam, const float* __restrict__ bet,
        const float* __restrict__ dt,  const float* __restrict__ lr_,
        const float* __restrict__ li_) {
    extern __shared__ float sm[];
    float *Er = sm, *Ei = Er+64*RP, *Dr = Ei+64*RP, *Di = Dr+64*RP;
    float *Xr = Di+64*RP, *Xi = Xr+64*RP;
    __shared__ float ps[4][64], pq[4][64], mb[64], rb[64];
    int pt = blockIdx.x, b = blockIdx.y, tid = threadIdx.x, hw0 = pt*64;
    for (int l = tid; l < 4096; l += 256) {
        int r_ = l>>6, c_ = l&63;
        Er[r_*RP+c_] = er[l];  Ei[r_*RP+c_] = ei[l];
        Dr[r_*RP+c_] = dmr[l]; Di[r_*RP+c_] = dmi[l];
    }
    int e0 = (tid>>4)*4, p0 = (tid&15)*4;
    // per-e recurrence params (e0..e0+3)
    float ddr[4], ddi[4], ffr[4], ffi[4];
    float dtb = dt[b];
    #pragma unroll
    for (int i = 0; i < 4; i++) {
        float lr = lr_[e0+i], li = li_[e0+i];
        float ex = expf(lr*dtb);
        float sn, cs; sincosf(li*dtb, &sn, &cs);
        ddr[i] = ex*cs; ddi[i] = ex*sn;
        float nr = ddr[i]-1.f, ni = ddi[i];
        float den = 1.f/(lr*lr + li*li);
        ffr[i] = (nr*lr + ni*li)*den;
        ffi[i] = (ni*lr - nr*li)*den;
    }
    u64 hrp[4][2] = {}, hip[4][2] = {};   // state h[e0+i][p0+2jp..]
    int lnp = tid & 63;
    for (int t = 0; t < NTT; t++) {
        int n = b*NTT + t;
        __syncthreads();   // Xr/Xi free (prev GEMM2 done)
        float sum = 0.f, sq = 0.f;
        for (int l = tid; l < 4096; l += 256) {
            int dd = l>>6, p = l&63;
            int gi_ = (n*ND+dd)*NHW + hw0 + p;
            float vr = g_a[gi_], vi = g_b[gi_];
            Xr[dd*RP+p] = vr; Xi[dd*RP+p] = vi;
            sum += vr + vi; sq += vr*vr + vi*vi;
        }
        ps[tid>>6][lnp] = sum; pq[tid>>6][lnp] = sq;
        __syncthreads();
        if (tid < 64) {
            float S = ps[0][tid]+ps[1][tid]+ps[2][tid]+ps[3][tid];
            float Q = pq[0][tid]+pq[1][tid]+pq[2][tid]+pq[3][tid];
            float m = S*(1.f/128.f);
            mb[tid] = m; rb[tid] = rsqrtf(Q*(1.f/128.f) - m*m + 1e-5f);
        }
        __syncthreads();
        {
            float m = mb[lnp], r = rb[lnp];
            for (int l = tid; l < 4096; l += 256) {
                int dd = l>>6, p = l&63;
                Xr[dd*RP+p] = (Xr[dd*RP+p] - m)*r*gam[dd]    + bet[dd];
                Xi[dd*RP+p] = (Xi[dd*RP+p] - m)*r*gam[dd+64] + bet[dd+64];
            }
        }
        __syncthreads();
        // GEMM-E: eig[e][p] = sum_d x[d][p] * E[d][e]
        u64 pr_[4][2] = {}, pi_[4][2] = {};
        for (int dd = 0; dd < 64; dd++) {
            u64 x0 = lds2(&Xr[dd*RP+p0]), x1 = lds2(&Xr[dd*RP+p0+2]);
            u64 y0 = lds2(&Xi[dd*RP+p0]), y1 = lds2(&Xi[dd*RP+p0+2]);
            float2 ea = *(const float2*)&Er[dd*RP+e0], eb = *(const float2*)&Er[dd*RP+e0+2];
            float2 qa = *(const float2*)&Ei[dd*RP+e0], qb = *(const float2*)&Ei[dd*RP+e0+2];
            float ers[4] = {ea.x, ea.y, eb.x, eb.y};
            float eis[4] = {qa.x, qa.y, qb.x, qb.y};
            #pragma unroll
            for (int i = 0; i < 4; i++) {
                u64 ber = bc(ers[i]), bei = bc(eis[i]), bnei = bc(-eis[i]);
                fma2(pr_[i][0], x0, ber); fma2(pr_[i][0], y0, bnei);
                fma2(pr_[i][1], x1, ber); fma2(pr_[i][1], y1, bnei);
                fma2(pi_[i][0], x0, bei); fma2(pi_[i][0], y0, ber);
                fma2(pi_[i][1], x1, bei); fma2(pi_[i][1], y1, ber);
            }
        }
        // recurrence update in registers: h = h*decay + u*forcing
        #pragma unroll
        for (int i = 0; i < 4; i++) {
            u64 bdr = bc(ddr[i]), bdi = bc(ddi[i]), bndi = bc(-ddi[i]);
            u64 bfr = bc(ffr[i]), bfi = bc(ffi[i]), bnfi = bc(-ffi[i]);
            #pragma unroll
            for (int jp = 0; jp < 2; jp++) {
                u64 nr_ = 0ull, ni_ = 0ull;
                fma2(nr_, hrp[i][jp], bdr); fma2(nr_, hip[i][jp], bndi);
                fma2(nr_, pr_[i][jp], bfr); fma2(nr_, pi_[i][jp], bnfi);
                fma2(ni_, hrp[i][jp], bdi); fma2(ni_, hip[i][jp], bdr);
                fma2(ni_, pr_[i][jp], bfi); fma2(ni_, pi_[i][jp], bfr);
                hrp[i][jp] = nr_; hip[i][jp] = ni_;
            }
        }
        __syncthreads();   // all GEMM-E reads of Xr/Xi done
        #pragma unroll
        for (int i = 0; i < 4; i++)
            for (int jp = 0; jp < 2; jp++) {
                *(float2*)&Xr[(e0+i)*RP + p0 + 2*jp] = up(hrp[i][jp]);
                *(float2*)&Xi[(e0+i)*RP + p0 + 2*jp] = up(hip[i][jp]);
            }
        __syncthreads();
        // GEMM-D (real part): out[c][p] = sum_e h[e][p]*Dr[e][c] - hi[e][p]*Di[e][c]
        u64 acc[4][2] = {};
        for (int e = 0; e < 64; e++) {
            u64 x0 = lds2(&Xr[e*RP+p0]), x1 = lds2(&Xr[e*RP+p0+2]);
            u64 y0 = lds2(&Xi[e*RP+p0]), y1 = lds2(&Xi[e*RP+p0+2]);
            float2 da = *(const float2*)&Dr[e*RP+e0], db = *(const float2*)&Dr[e*RP+e0+2];
            float2 qa = *(const float2*)&Di[e*RP+e0], qb = *(const float2*)&Di[e*RP+e0+2];
            float drs[4] = {da.x, da.y, db.x, db.y};
            float dis[4] = {qa.x, qa.y, qb.x, qb.y};
            #pragma unroll
            for (int i = 0; i < 4; i++) {
                u64 bdr = bc(drs[i]), bnd = bc(-dis[i]);
                fma2(acc[i][0], x0, bdr); fma2(acc[i][0], y0, bnd);
                fma2(acc[i][1], x1, bdr); fma2(acc[i][1], y1, bnd);
            }
        }
        // + residual (reload x1 real from g_a, L2-hot) -> g_c
        #pragma unroll
        for (int i = 0; i < 4; i++)
            for (int jp = 0; jp < 2; jp++) {
                int gi_ = (n*ND + e0+i)*NHW + hw0 + p0 + 2*jp;
                float2 v = up(acc[i][jp]);
                float2 rs = *(const float2*)&g_a[gi_];
                v.x += rs.x; v.y += rs.y;
                *(float2*)&g_c[gi_] = v;
            }
    }
}

// ---------- fast gelu ----------
__device__ __forceinline__ float gelu_f(float x) {
    float u = 0.7978845608028654f*(x + 0.044715f*x*x*x);
    return x * (1.f - __fdividef(1.f, __expf(2.f*u) + 1.f));
}

// ---------- fused MLP 128 -> 512(gelu) -> 128 + residual, f chunked by 64 ----------
#define MLP_SM ((128*66 + 64*66 + 8448)*4)
__global__ __launch_bounds__(256) void k_mlp(const float* __restrict__ w1,
                                             const float* __restrict__ b1,
                                             const float* __restrict__ w2,
                                             const float* __restrict__ b2,
                                             float* __restrict__ out) {
    extern __shared__ float sm[];
    float *Xs = sm;                // [128][66]
    float *Hs = Xs + 128*66;       // [64][66]
    float *Ws = Hs + 64*66;        // w1 chunk [128][66] or w2 chunk [64][130]
    int pt = blockIdx.x, n = blockIdx.y, tid = threadIdx.x, hw0 = pt*64;
    for (int l = tid; l < 128*64; l += 256) {
        int c = l>>6, p = l&63;
        float v = (c < 64) ? g_c[(n*ND+c)*NHW + hw0 + p]
                           : g_b[(n*ND+c-64)*NHW + hw0 + p];
        Xs[c*66+p] = v;
    }
    int fg = (tid>>4)*4, p0 = (tid&15)*4;
    int c8 = (tid>>4)*8;
    u64 accp[4][4];
    #pragma unroll
    for (int i = 0; i < 4; i++)
        for (int j = 0; j < 4; j++) accp[i][j] = 0ull;
    for (int fc = 0; fc < 8; fc++) {
        __syncthreads();
        for (int l = tid; l < 128*64; l += 256) {
            int c = l>>6, f = l&63;
            Ws[c*66+f] = w1[c*512 + fc*64 + f];
        }
        __syncthreads();
        u64 a2p[2][4];
        #pragma unroll
        for (int i = 0; i < 2; i++)
            for (int j = 0; j < 4; j++) a2p[i][j] = 0ull;
        for (int c = 0; c < 128; c++) {
            float2 x01 = *(const float2*)&Xs[c*66+p0];
            float2 x23 = *(const float2*)&Xs[c*66+p0+2];
            u64 bx[4] = {bc(x01.x), bc(x01.y), bc(x23.x), bc(x23.y)};
            u64 w01 = lds2(&Ws[c*66+fg]), w23 = lds2(&Ws[c*66+fg+2]);
            fma2(a2p[0][0], w01, bx[0]); fma2(a2p[0][1], w01, bx[1]);
            fma2(a2p[0][2], w01, bx[2]); fma2(a2p[0][3], w01, bx[3]);
            fma2(a2p[1][0], w23, bx[0]); fma2(a2p[1][1], w23, bx[1]);
            fma2(a2p[1][2], w23, bx[2]); fma2(a2p[1][3], w23, bx[3]);
        }
        __syncthreads();
        #pragma unroll
        for (int ip = 0; ip < 2; ip++) {
            int fA = fg + 2*ip, fB = fA + 1;
            float biasA = b1[fc*64 + fA], biasB = b1[fc*64 + fB];
            float2 v0 = up(a2p[ip][0]), v1 = up(a2p[ip][1]);
            float2 v2 = up(a2p[ip][2]), v3 = up(a2p[ip][3]);
            Hs[fA*66 + p0]   = gelu_f(v0.x + biasA);
            Hs[fA*66 + p0+1] = gelu_f(v1.x + biasA);
            Hs[fA*66 + p0+2] = gelu_f(v2.x + biasA);
            Hs[fA*66 + p0+3] = gelu_f(v3.x + biasA);
            Hs[fB*66 + p0]   = gelu_f(v0.y + biasB);
            Hs[fB*66 + p0+1] = gelu_f(v1.y + biasB);
            Hs[fB*66 + p0+2] = gelu_f(v2.y + biasB);
            Hs[fB*66 + p0+3] = gelu_f(v3.y + biasB);
        }
        for (int l = tid; l < 64*128; l += 256) {
            int f = l>>7, c = l&127;
            Ws[f*130+c] = w2[(fc*64+f)*128 + c];
        }
        __syncthreads();
        for (int f = 0; f < 64; f++) {
            float2 h01 = *(const float2*)&Hs[f*66+p0];
            float2 h23 = *(const float2*)&Hs[f*66+p0+2];
            u64 bh[4] = {bc(h01.x), bc(h01.y), bc(h23.x), bc(h23.y)};
            const u64* wp = (const u64*)&Ws[f*130+c8];
            #pragma unroll
            for (int ip = 0; ip < 4; ip++) {
                u64 wv = wp[ip];
                fma2(accp[ip][0], wv, bh[0]); fma2(accp[ip][1], wv, bh[1]);
                fma2(accp[ip][2], wv, bh[2]); fma2(accp[ip][3], wv, bh[3]);
            }
        }
    }
    #pragma unroll
    for (int ip = 0; ip < 4; ip++) {
        int cA = c8 + 2*ip, cB = cA + 1;
        float bA = b2[cA], bB = b2[cB];
        #pragma unroll
        for (int j = 0; j < 4; j++) {
            float2 v = up(accp[ip][j]);
            int p = p0 + j;
            float resA = (cA < 64) ? g_c[(n*ND+cA)*NHW + hw0 + p]
                                   : g_b[(n*ND+cA-64)*NHW + hw0 + p];
            float resB = (cB < 64) ? g_c[(n*ND+cB)*NHW + hw0 + p]
                                   : g_b[(n*ND+cB-64)*NHW + hw0 + p];
            out[((size_t)n*ND2 + cA)*NHW + hw0 + p] = v.x + bA + resA;
            out[((size_t)n*ND2 + cB)*NHW + hw0 + p] = v.y + bB + resB;
        }
    }
}

extern "C" void kernel_launch(void* const* d_in, const int* in_sizes, int n_in,
                              void* d_out, int out_size) {
    const float* xr   = (const float*)d_in[0];
    const float* xi   = (const float*)d_in[1];
    const float* dt   = (const float*)d_in[2];
    const float* lsg  = (const float*)d_in[3];
    const float* lsb  = (const float*)d_in[4];
    const float* cw   = (const float*)d_in[5];
    const float* cb   = (const float*)d_in[6];
    const float* swr  = (const float*)d_in[7];
    const float* swi  = (const float*)d_in[8];
    const float* gate = (const float*)d_in[9];
    const float* ltg  = (const float*)d_in[10];
    const float* ltb  = (const float*)d_in[11];
    const float* lamr = (const float*)d_in[12];
    const float* lami = (const float*)d_in[13];
    const float* enr  = (const float*)d_in[14];
    const float* eni  = (const float*)d_in[15];
    const float* dcr  = (const float*)d_in[16];
    const float* dci  = (const float*)d_in[17];
    const float* w1   = (const float*)d_in[18];
    const float* b1   = (const float*)d_in[19];
    const float* w2   = (const float*)d_in[20];
    const float* b2   = (const float*)d_in[21];
    float* out = (float*)d_out;

    cudaFuncSetAttribute(k_conv,     cudaFuncAttributeMaxDynamicSharedMemorySize, CONV_SM);
    cudaFuncSetAttribute(k_fft,      cudaFuncAttributeMaxDynamicSharedMemorySize, FFT_SM);
    cudaFuncSetAttribute(k_temporal, cudaFuncAttributeMaxDynamicSharedMemorySize, TEMP_SM);
    cudaFuncSetAttribute(k_mlp,      cudaFuncAttributeMaxDynamicSharedMemorySize, MLP_SM);

    dim3 gHN(64, 64);
    k_init<<<(128*128*9 + 255)/256, 256>>>(cw);
    k_ln0<<<gHN, dim3(64,4)>>>(xr, xi, lsg, lsb);
    k_conv<<<gHN, 256, CONV_SM>>>(cb);
    k_fft<<<gHN, 256, FFT_SM>>>(swr, swi, xr, xi, gate);
    k_temporal<<<dim3(64, NBB), 256, TEMP_SM>>>(enr, eni, dcr, dci, ltg, ltb, dt, lamr, lami);
    k_mlp<<<gHN, 256, MLP_SM>>>(w1, b1, w2, b2, out);
}